// round 4
// baseline (speedup 1.0000x reference)
#include <cuda_runtime.h>
#include <cuda_bf16.h>
#include <math.h>

#define BB 32
#define TT 2048
#define FF 512
#define HH 512
#define G4 (4*HH)
#define NCTA 128

typedef unsigned long long u64;

// ---------------- scratch ----------------
__device__ float g_xg[(size_t)TT * BB * G4];   // [T][B][4H]
__device__ float g_hbuf[2][BB * HH];           // ping-pong h
__device__ int g_bar[TT];

// ---------------- packed f32x2 + fast-math helpers ----------------
__device__ __forceinline__ u64 f2dup(float v) {
    u64 r; asm("mov.b64 %0, {%1, %1};" : "=l"(r) : "f"(v)); return r;
}
__device__ __forceinline__ u64 fma2(u64 a, u64 b, u64 c) {
    u64 d; asm("fma.rn.f32x2 %0, %1, %2, %3;" : "=l"(d) : "l"(a), "l"(b), "l"(c)); return d;
}
__device__ __forceinline__ float2 unpack2(u64 v) {
    float2 r; asm("mov.b64 {%0, %1}, %2;" : "=f"(r.x), "=f"(r.y) : "l"(v)); return r;
}
__device__ __forceinline__ float fex2(float x) {
    float r; asm("ex2.approx.f32 %0, %1;" : "=f"(r) : "f"(x)); return r;
}
__device__ __forceinline__ float frcp(float x) {
    float r; asm("rcp.approx.f32 %0, %1;" : "=f"(r) : "f"(x)); return r;
}
#define LOG2E 1.4426950408889634f
__device__ __forceinline__ float fsig(float x) { return frcp(1.f + fex2(-LOG2E * x)); }
__device__ __forceinline__ float ftanh(float x) { return 2.f * frcp(1.f + fex2(-2.f * LOG2E * x)) - 1.f; }

// ---------------- GEMM: Xg = x @ Wi + bias (double-buffered, FFMA2) ----------------
// Also re-zeros the grid-barrier counters (replay safety) — gemm completes
// before lstm_rec launches (stream order), so this is race-free.
__global__ __launch_bounds__(256) void gemm_xwi(
    const float* __restrict__ x, const float* __restrict__ Wi,
    const float* __restrict__ bias)
{
    __shared__ u64   asd[2][8][128];
    __shared__ float bsd[2][8][128];

    const int tid = threadIdx.x;
    if (blockIdx.y == 0 && blockIdx.x < 8) {
        g_bar[blockIdx.x * 256 + tid] = 0;
    }

    const int tx = tid & 15;
    const int ty = tid >> 4;
    const int row0 = blockIdx.y * 128;
    const int col0 = blockIdx.x * 128;

    const int ar = tid >> 1, ac = tid & 1;
    const int br = tid >> 5, bc = tid & 31;

    const float* aptr = x + (size_t)(row0 + ar) * FF + ac * 4;
    const float* bptr = Wi + (size_t)br * G4 + col0 + bc * 4;

    float4 av = *(const float4*)aptr;
    float4 bv = *(const float4*)bptr;

    u64 acc[8][4];
#pragma unroll
    for (int i = 0; i < 8; i++)
#pragma unroll
        for (int j = 0; j < 4; j++) acc[i][j] = 0ull;

    int p = 0;
    for (int s = 0; s < 64; s++) {
        asd[p][ac * 4 + 0][ar] = f2dup(av.x);
        asd[p][ac * 4 + 1][ar] = f2dup(av.y);
        asd[p][ac * 4 + 2][ar] = f2dup(av.z);
        asd[p][ac * 4 + 3][ar] = f2dup(av.w);
        *(float4*)&bsd[p][br][bc * 4] = bv;
        __syncthreads();
        if (s < 63) {
            av = *(const float4*)(aptr + (s + 1) * 8);
            bv = *(const float4*)(bptr + (size_t)(s + 1) * 8 * G4);
        }
#pragma unroll
        for (int kk = 0; kk < 8; kk++) {
            const ulonglong2* ap2 = (const ulonglong2*)&asd[p][kk][ty * 8];
            ulonglong2 q0 = ap2[0], q1 = ap2[1], q2 = ap2[2], q3 = ap2[3];
            const ulonglong2* bp2 = (const ulonglong2*)&bsd[p][kk][tx * 8];
            ulonglong2 r0 = bp2[0], r1 = bp2[1];
            u64 aa[8] = {q0.x, q0.y, q1.x, q1.y, q2.x, q2.y, q3.x, q3.y};
            u64 bb2[4] = {r0.x, r0.y, r1.x, r1.y};
#pragma unroll
            for (int i = 0; i < 8; i++)
#pragma unroll
                for (int j = 0; j < 4; j++)
                    acc[i][j] = fma2(aa[i], bb2[j], acc[i][j]);
        }
        __syncthreads();
        p ^= 1;
    }

    const int cbase = col0 + tx * 8;
    float4 bia0 = *(const float4*)(bias + cbase);
    float4 bia1 = *(const float4*)(bias + cbase + 4);
#pragma unroll
    for (int i = 0; i < 8; i++) {
        int r = row0 + ty * 8 + i;
        int bidx = r >> 11;
        int t = r & (TT - 1);
        float* dst = g_xg + (size_t)t * (BB * G4) + (size_t)bidx * G4 + cbase;
        float2 p0 = unpack2(acc[i][0]);
        float2 p1 = unpack2(acc[i][1]);
        float2 p2 = unpack2(acc[i][2]);
        float2 p3 = unpack2(acc[i][3]);
        float4 v0, v1;
        v0.x = p0.x + bia0.x; v0.y = p0.y + bia0.y;
        v0.z = p1.x + bia0.z; v0.w = p1.y + bia0.w;
        v1.x = p2.x + bia1.x; v1.y = p2.y + bia1.y;
        v1.z = p3.x + bia1.z; v1.w = p3.y + bia1.w;
        *(float4*)(dst) = v0;
        *(float4*)(dst + 4) = v1;
    }
}

// ---------------- persistent recurrent kernel ----------------
// 128 CTAs x 256 threads. CTA owns j0..j0+3 (16 z columns).
// Thread (b=tid>>3, jj=(tid>>1)&3, gp=tid&1) computes gates {2gp, 2gp+1} of
// (b, j0+jj) over the FULL K=512 — no cross-thread reduction; partner gate
// exchange via shfl.bfly. h is read straight from global (L1-cached; tid0's
// per-step gpu fence emits CCTL.IVALL so L1 is never stale).
// SMEM (static, 32KB): w[k4][half][slot] float4,
//   slot = jj*2+gp, half = gate&1, gate = 2*(slot&1)+half.
__shared__ float4 wsm4_s[128 * 16];

__global__ __launch_bounds__(256, 1) void lstm_rec(
    const float* __restrict__ Wh,
    const float* __restrict__ c0, const float* __restrict__ h0,
    float* __restrict__ out)
{
    __shared__ float4 wsm4[128 * 16];

    const int tid = threadIdx.x;
    const int cta = blockIdx.x;
    const int j0 = cta * 4;

    // Wh slice -> SMEM (8192 floats)
    // dest float s -> kk=s&3, float4 q=s>>2: slot=q&7, half=(q>>3)&1, k4=q>>4
    float* wsc = (float*)wsm4;
    for (int s = tid; s < 8192; s += 256) {
        int kk = s & 3;
        int q = s >> 2;
        int slot = q & 7, half = (q >> 3) & 1, k4v = q >> 4;
        int jj_s = slot >> 1, gp_s = slot & 1;
        int gate = gp_s * 2 + half;
        wsc[s] = Wh[(size_t)(k4v * 4 + kk) * G4 + gate * HH + j0 + jj_s];
    }

    const int b  = tid >> 3;
    const int jj = (tid >> 1) & 3;
    const int gp = tid & 1;
    const int j  = j0 + jj;
    const int slot = jj * 2 + gp;

    float creg = 0.f;
    if (gp == 0) creg = c0[b * HH + j];

    float* outc = out;
    float* outh = out + BB * HH;
    float* ys   = out + 2 * BB * HH;

    const ulonglong2* wbase = (const ulonglong2*)wsm4 + slot;

    __syncthreads();

    for (int t = 0; t < TT; t++) {
        const float* hsrc = (t == 0) ? h0 : g_hbuf[t & 1];
        const ulonglong2* hrow = (const ulonglong2*)(hsrc + b * HH);

        // prefetch xg (independent of h; completes under the dot)
        const float* xr = g_xg + (size_t)t * (BB * G4) + (size_t)b * G4 + j;
        float xga = __ldg(xr + (2 * gp) * HH);
        float xgb = __ldg(xr + (2 * gp + 1) * HH);

        u64 acc0 = 0ull, acc1 = 0ull;
#pragma unroll 4
        for (int k4 = 0; k4 < 128; k4++) {
            ulonglong2 hv = hrow[k4];
            ulonglong2 w0 = wbase[k4 * 16];
            ulonglong2 w1 = wbase[k4 * 16 + 8];
            acc0 = fma2(hv.x, w0.x, acc0);
            acc0 = fma2(hv.y, w0.y, acc0);
            acc1 = fma2(hv.x, w1.x, acc1);
            acc1 = fma2(hv.y, w1.y, acc1);
        }

        float2 a0 = unpack2(acc0);
        float2 a1 = unpack2(acc1);
        float za = a0.x + a0.y + xga;   // gate 2gp
        float zb = a1.x + a1.y + xgb;   // gate 2gp+1
        float pa = __shfl_xor_sync(0xffffffffu, za, 1);
        float pb = __shfl_xor_sync(0xffffffffu, zb, 1);

        if (gp == 0) {
            // this thread: za=i, zb=f; partner: pa=g, pb=o
            float ig = fsig(za);
            float fg = fsig(zb);
            float gg = ftanh(pa);
            float og = fsig(pb);
            creg = fg * creg + ig * gg;
            float hnew = og * ftanh(creg);
            g_hbuf[(t + 1) & 1][b * HH + j] = hnew;
            ys[(size_t)b * (TT * HH) + (size_t)t * HH + j] = hnew;
            if (t == TT - 1) {
                outc[b * HH + j] = creg;
                outh[b * HH + j] = hnew;
            }
        }

        // grid barrier: release-add, acquire-poll, then one gpu fence
        // (CCTL.IVALL -> L1 can't serve stale h next step)
        __syncthreads();
        if (tid == 0) {
            int* barp = &g_bar[t];
            asm volatile("red.release.gpu.global.add.s32 [%0], 1;"
                         :: "l"(barp) : "memory");
            int v;
            do {
                asm volatile("ld.acquire.gpu.global.s32 %0, [%1];"
                             : "=r"(v) : "l"(barp) : "memory");
            } while (v < NCTA);
            __threadfence();
        }
        __syncthreads();
    }
}

// ---------------- launcher ----------------
extern "C" void kernel_launch(void* const* d_in, const int* in_sizes, int n_in,
                              void* d_out, int out_size)
{
    const float* x    = (const float*)d_in[0];
    const float* c0   = (const float*)d_in[1];
    const float* h0   = (const float*)d_in[2];
    const float* Wi   = (const float*)d_in[3];
    const float* Wh   = (const float*)d_in[4];
    const float* bias = (const float*)d_in[5];
    float* out = (float*)d_out;

    gemm_xwi<<<dim3(G4 / 128, (BB * TT) / 128), 256>>>(x, Wi, bias);
    lstm_rec<<<NCTA, 256>>>(Wh, c0, h0, out);
}

// round 5
// speedup vs baseline: 2.0890x; 2.0890x over previous
#include <cuda_runtime.h>
#include <cuda_bf16.h>
#include <math.h>

#define BB 32
#define TT 2048
#define FF 512
#define HH 512
#define G4 (4*HH)
#define NCTA 128

typedef unsigned long long u64;

// ---------------- scratch ----------------
__device__ float g_xg[(size_t)TT * BB * G4];   // [T][B][4H]
__device__ float g_hbuf[2][BB * HH];           // ping-pong h
__device__ int g_bar[TT];

// ---------------- packed f32x2 + fast-math helpers ----------------
__device__ __forceinline__ u64 f2dup(float v) {
    u64 r; asm("mov.b64 %0, {%1, %1};" : "=l"(r) : "f"(v)); return r;
}
__device__ __forceinline__ u64 fma2(u64 a, u64 b, u64 c) {
    u64 d; asm("fma.rn.f32x2 %0, %1, %2, %3;" : "=l"(d) : "l"(a), "l"(b), "l"(c)); return d;
}
__device__ __forceinline__ u64 add2(u64 a, u64 b) {
    u64 d; asm("add.rn.f32x2 %0, %1, %2;" : "=l"(d) : "l"(a), "l"(b)); return d;
}
__device__ __forceinline__ float2 unpack2(u64 v) {
    float2 r; asm("mov.b64 {%0, %1}, %2;" : "=f"(r.x), "=f"(r.y) : "l"(v)); return r;
}
__device__ __forceinline__ float fex2(float x) {
    float r; asm("ex2.approx.f32 %0, %1;" : "=f"(r) : "f"(x)); return r;
}
__device__ __forceinline__ float frcp(float x) {
    float r; asm("rcp.approx.f32 %0, %1;" : "=f"(r) : "f"(x)); return r;
}
#define LOG2E 1.4426950408889634f
__device__ __forceinline__ float fsig(float x) { return frcp(1.f + fex2(-LOG2E * x)); }
__device__ __forceinline__ float ftanh(float x) { return 2.f * frcp(1.f + fex2(-2.f * LOG2E * x)) - 1.f; }

// ---------------- GEMM: Xg = x @ Wi + bias (double-buffered, FFMA2) ----------------
// Also re-zeros the grid-barrier counters (replay safety; gemm finishes before
// lstm_rec launches in stream order).
__global__ __launch_bounds__(256) void gemm_xwi(
    const float* __restrict__ x, const float* __restrict__ Wi,
    const float* __restrict__ bias)
{
    __shared__ u64   asd[2][8][128];
    __shared__ float bsd[2][8][128];

    const int tid = threadIdx.x;
    if (blockIdx.y == 0 && blockIdx.x < 8) {
        g_bar[blockIdx.x * 256 + tid] = 0;
    }

    const int tx = tid & 15;
    const int ty = tid >> 4;
    const int row0 = blockIdx.y * 128;
    const int col0 = blockIdx.x * 128;

    const int ar = tid >> 1, ac = tid & 1;
    const int br = tid >> 5, bc = tid & 31;

    const float* aptr = x + (size_t)(row0 + ar) * FF + ac * 4;
    const float* bptr = Wi + (size_t)br * G4 + col0 + bc * 4;

    float4 av = *(const float4*)aptr;
    float4 bv = *(const float4*)bptr;

    u64 acc[8][4];
#pragma unroll
    for (int i = 0; i < 8; i++)
#pragma unroll
        for (int j = 0; j < 4; j++) acc[i][j] = 0ull;

    int p = 0;
    for (int s = 0; s < 64; s++) {
        asd[p][ac * 4 + 0][ar] = f2dup(av.x);
        asd[p][ac * 4 + 1][ar] = f2dup(av.y);
        asd[p][ac * 4 + 2][ar] = f2dup(av.z);
        asd[p][ac * 4 + 3][ar] = f2dup(av.w);
        *(float4*)&bsd[p][br][bc * 4] = bv;
        __syncthreads();
        if (s < 63) {
            av = *(const float4*)(aptr + (s + 1) * 8);
            bv = *(const float4*)(bptr + (size_t)(s + 1) * 8 * G4);
        }
#pragma unroll
        for (int kk = 0; kk < 8; kk++) {
            const ulonglong2* ap2 = (const ulonglong2*)&asd[p][kk][ty * 8];
            ulonglong2 q0 = ap2[0], q1 = ap2[1], q2 = ap2[2], q3 = ap2[3];
            const ulonglong2* bp2 = (const ulonglong2*)&bsd[p][kk][tx * 8];
            ulonglong2 r0 = bp2[0], r1 = bp2[1];
            u64 aa[8] = {q0.x, q0.y, q1.x, q1.y, q2.x, q2.y, q3.x, q3.y};
            u64 bb2[4] = {r0.x, r0.y, r1.x, r1.y};
#pragma unroll
            for (int i = 0; i < 8; i++)
#pragma unroll
                for (int j = 0; j < 4; j++)
                    acc[i][j] = fma2(aa[i], bb2[j], acc[i][j]);
        }
        __syncthreads();
        p ^= 1;
    }

    const int cbase = col0 + tx * 8;
    float4 bia0 = *(const float4*)(bias + cbase);
    float4 bia1 = *(const float4*)(bias + cbase + 4);
#pragma unroll
    for (int i = 0; i < 8; i++) {
        int r = row0 + ty * 8 + i;
        int bidx = r >> 11;
        int t = r & (TT - 1);
        float* dst = g_xg + (size_t)t * (BB * G4) + (size_t)bidx * G4 + cbase;
        float2 p0 = unpack2(acc[i][0]);
        float2 p1 = unpack2(acc[i][1]);
        float2 p2 = unpack2(acc[i][2]);
        float2 p3 = unpack2(acc[i][3]);
        float4 v0, v1;
        v0.x = p0.x + bia0.x; v0.y = p0.y + bia0.y;
        v0.z = p1.x + bia0.z; v0.w = p1.y + bia0.w;
        v1.x = p2.x + bia1.x; v1.y = p2.y + bia1.y;
        v1.z = p3.x + bia1.z; v1.w = p3.y + bia1.w;
        *(float4*)(dst) = v0;
        *(float4*)(dst + 4) = v1;
    }
}

// ---------------- persistent recurrent kernel (round-3 dot, light overhead) ----
#define SMEM_HS_BYTES   (32 * 129 * 16)          // 66048
#define SMEM_W_BYTES    (128 * 16 * 16)          // 32768
#define SMEM_PART_BYTES (256 * 17 * 8)           // 34816
#define SMEM_REC_BYTES  (SMEM_HS_BYTES + SMEM_W_BYTES + SMEM_PART_BYTES)

__global__ __launch_bounds__(256, 1) void lstm_rec(
    const float* __restrict__ Wh,
    const float* __restrict__ c0, const float* __restrict__ h0,
    float* __restrict__ out)
{
    extern __shared__ char smraw[];
    float4* hs4  = (float4*)smraw;                                  // [32*129]
    float4* wsm4 = (float4*)(smraw + SMEM_HS_BYTES);                // [2048]
    u64*    part2 = (u64*)(smraw + SMEM_HS_BYTES + SMEM_W_BYTES);   // [256*17]

    const int tid = threadIdx.x;
    const int cta = blockIdx.x;
    const int j0 = cta * 4;

    // Wh slice -> SMEM (8192 floats): s = (k4*16 + gate*4 + jj)*4 + kk
    float* wsc = (float*)wsm4;
    for (int s = tid; s < 8192; s += 256) {
        int kk = s & 3, jj = (s >> 2) & 3, gate = (s >> 4) & 3, k4v = s >> 6;
        wsc[s] = Wh[(size_t)(k4v * 4 + kk) * G4 + gate * HH + j0 + jj];
    }

    // dot-thread mapping
    const int ks = tid >> 5, lane = tid & 31, bg = lane >> 2, cg = lane & 3;
    // reducer mapping (tid < 128)
    const int bg_r = tid >> 4, cg_r = (tid >> 2) & 3, ib_r = tid & 3;
    const int b_r = ib_r * 8 + bg_r;
    const int j_r = j0 + cg_r;

    float creg = 0.f;
    if (tid < 128) creg = c0[b_r * HH + j_r];

    float* outc = out;
    float* outh = out + BB * HH;
    float* ys   = out + 2 * BB * HH;

    for (int t = 0; t < TT; t++) {
        // cooperative h load (volatile -> always L2-fresh), conflict-free store
        const float4* hsrc = (t == 0) ? (const float4*)h0 : (const float4*)g_hbuf[t & 1];
#pragma unroll
        for (int m = 0; m < 16; m++) {
            int f4 = tid + m * 256;
            int bb = f4 >> 7;
            int k4 = f4 & 127;
            hs4[bb * 129 + k4] = __ldcv(hsrc + f4);
        }
        // xg prefetch (latency hides under the dot)
        float xq0 = 0.f, xq1 = 0.f, xq2 = 0.f, xq3 = 0.f;
        if (tid < 128) {
            const float* xr = g_xg + (size_t)t * (BB * G4) + (size_t)b_r * G4 + j_r;
            xq0 = __ldg(xr);
            xq1 = __ldg(xr + HH);
            xq2 = __ldg(xr + 2 * HH);
            xq3 = __ldg(xr + 3 * HH);
        }
        __syncthreads();

        // 4b x 4col x 64k outer-product dot, packed f32x2 over k pairs
        u64 acc[4][4];
#pragma unroll
        for (int i = 0; i < 4; i++)
#pragma unroll
            for (int j = 0; j < 4; j++) acc[i][j] = 0ull;

        const int kbase = ks * 16;
#pragma unroll 4
        for (int kq = 0; kq < 16; kq++) {
            int k4 = kbase + kq;
            const ulonglong2* wr = (const ulonglong2*)wsm4 + k4 * 16 + cg;
            ulonglong2 wv0 = wr[0];
            ulonglong2 wv1 = wr[4];
            ulonglong2 wv2 = wr[8];
            ulonglong2 wv3 = wr[12];
            const ulonglong2* hr = (const ulonglong2*)hs4 + bg * 129 + k4;
            ulonglong2 hv0 = hr[0];
            ulonglong2 hv1 = hr[8 * 129];
            ulonglong2 hv2 = hr[16 * 129];
            ulonglong2 hv3 = hr[24 * 129];

            acc[0][0] = fma2(hv0.x, wv0.x, acc[0][0]); acc[0][0] = fma2(hv0.y, wv0.y, acc[0][0]);
            acc[0][1] = fma2(hv0.x, wv1.x, acc[0][1]); acc[0][1] = fma2(hv0.y, wv1.y, acc[0][1]);
            acc[0][2] = fma2(hv0.x, wv2.x, acc[0][2]); acc[0][2] = fma2(hv0.y, wv2.y, acc[0][2]);
            acc[0][3] = fma2(hv0.x, wv3.x, acc[0][3]); acc[0][3] = fma2(hv0.y, wv3.y, acc[0][3]);

            acc[1][0] = fma2(hv1.x, wv0.x, acc[1][0]); acc[1][0] = fma2(hv1.y, wv0.y, acc[1][0]);
            acc[1][1] = fma2(hv1.x, wv1.x, acc[1][1]); acc[1][1] = fma2(hv1.y, wv1.y, acc[1][1]);
            acc[1][2] = fma2(hv1.x, wv2.x, acc[1][2]); acc[1][2] = fma2(hv1.y, wv2.y, acc[1][2]);
            acc[1][3] = fma2(hv1.x, wv3.x, acc[1][3]); acc[1][3] = fma2(hv1.y, wv3.y, acc[1][3]);

            acc[2][0] = fma2(hv2.x, wv0.x, acc[2][0]); acc[2][0] = fma2(hv2.y, wv0.y, acc[2][0]);
            acc[2][1] = fma2(hv2.x, wv1.x, acc[2][1]); acc[2][1] = fma2(hv2.y, wv1.y, acc[2][1]);
            acc[2][2] = fma2(hv2.x, wv2.x, acc[2][2]); acc[2][2] = fma2(hv2.y, wv2.y, acc[2][2]);
            acc[2][3] = fma2(hv2.x, wv3.x, acc[2][3]); acc[2][3] = fma2(hv2.y, wv3.y, acc[2][3]);

            acc[3][0] = fma2(hv3.x, wv0.x, acc[3][0]); acc[3][0] = fma2(hv3.y, wv0.y, acc[3][0]);
            acc[3][1] = fma2(hv3.x, wv1.x, acc[3][1]); acc[3][1] = fma2(hv3.y, wv1.y, acc[3][1]);
            acc[3][2] = fma2(hv3.x, wv2.x, acc[3][2]); acc[3][2] = fma2(hv3.y, wv2.y, acc[3][2]);
            acc[3][3] = fma2(hv3.x, wv3.x, acc[3][3]); acc[3][3] = fma2(hv3.y, wv3.y, acc[3][3]);
        }

#pragma unroll
        for (int i = 0; i < 4; i++)
#pragma unroll
            for (int j = 0; j < 4; j++)
                part2[tid * 17 + i * 4 + j] = acc[i][j];
        __syncthreads();

        if (tid < 128) {
            const int pbase = bg_r * 4 + cg_r;
            float z[4];
#pragma unroll
            for (int g = 0; g < 4; g++) {
                u64 s = part2[pbase * 17 + ib_r * 4 + g];
#pragma unroll
                for (int kk2 = 1; kk2 < 8; kk2++)
                    s = add2(s, part2[(kk2 * 32 + pbase) * 17 + ib_r * 4 + g]);
                float2 uv = unpack2(s);
                z[g] = uv.x + uv.y;
            }
            float ig = fsig(z[0] + xq0);
            float fg = fsig(z[1] + xq1);
            float gg = ftanh(z[2] + xq2);
            float og = fsig(z[3] + xq3);
            creg = fg * creg + ig * gg;
            float hnew = og * ftanh(creg);
            g_hbuf[(t + 1) & 1][b_r * HH + j_r] = hnew;
            ys[(size_t)b_r * (TT * HH) + (size_t)t * HH + j_r] = hnew;
            if (t == TT - 1) {
                outc[b_r * HH + j_r] = creg;
                outh[b_r * HH + j_r] = hnew;
            }
        }

        // grid barrier: tid0-only release-add + acquire-poll (no per-thread fences)
        __syncthreads();
        if (tid == 0) {
            int* barp = &g_bar[t];
            asm volatile("red.release.gpu.global.add.s32 [%0], 1;"
                         :: "l"(barp) : "memory");
            int v;
            do {
                asm volatile("ld.acquire.gpu.global.s32 %0, [%1];"
                             : "=r"(v) : "l"(barp) : "memory");
            } while (v < NCTA);
        }
        __syncthreads();
    }
}

// ---------------- launcher ----------------
extern "C" void kernel_launch(void* const* d_in, const int* in_sizes, int n_in,
                              void* d_out, int out_size)
{
    const float* x    = (const float*)d_in[0];
    const float* c0   = (const float*)d_in[1];
    const float* h0   = (const float*)d_in[2];
    const float* Wi   = (const float*)d_in[3];
    const float* Wh   = (const float*)d_in[4];
    const float* bias = (const float*)d_in[5];
    float* out = (float*)d_out;

    cudaFuncSetAttribute(lstm_rec, cudaFuncAttributeMaxDynamicSharedMemorySize,
                         SMEM_REC_BYTES);

    gemm_xwi<<<dim3(G4 / 128, (BB * TT) / 128), 256>>>(x, Wi, bias);
    lstm_rec<<<NCTA, 256, SMEM_REC_BYTES>>>(Wh, c0, h0, out);
}